// round 8
// baseline (speedup 1.0000x reference)
#include <cuda_runtime.h>

#define NN   64
#define TT   128
#define NBR  16
#define NB2  32
#define NP   256
#define NS   255
#define BIGF 1e30f
#define FULLMASK 0xFFFFFFFFu

__device__ __align__(16) float g_proj[NN * NB2 * TT * 3];
__device__ float g_cost[NN * NB2];
__device__ int   g_cnt[NN];          // zero-init; picker resets each launch

__global__ __launch_bounds__(256)
void fused_arc_kernel(const float* __restrict__ traj,
                      const float* __restrict__ road,
                      const unsigned char* __restrict__ maskraw,
                      float* __restrict__ out)
{
    __shared__ __align__(16) float rpt[NP * 3];    // road pts AoS [p*3+c]
    __shared__ __align__(16) float tbuf[TT * 3];   // traj pts AoS
    __shared__ __align__(16) float stage[2 * TT * 3]; // proj staging (fwd|bwd)
    __shared__ unsigned char rm[NP];
    __shared__ float sl[NP];           // fwd seg len (0 invalid); sl[255]=0
    __shared__ float cum[NP];          // inclusive scan of sl; cum_s(i)= i? cum[i-1]:0
    __shared__ float tcs_s[TT];        // inclusive scan of traj seg len
    __shared__ float wsA[8], wsB[8];
    __shared__ float wsum[8];
    __shared__ unsigned long long s_key;   // (d2bits<<32)|segidx
    __shared__ int   s_mn, s_mx;
    __shared__ int   sh_pick, sh_b, sh_hasb;

    const int tid  = threadIdx.x;
    const int lane = tid & 31;
    const int w    = tid >> 5;
    const int b    = blockIdx.x;       // undirected branch 0..15
    const int n    = blockIdx.y;

    if (tid == 0) {
        s_key = ~0ull;
        s_mn  = NS;
        s_mx  = 0;
    }

    // ---- coalesced loads (float4): threads 0-191 road (192 f4), 160-255 traj (96 f4)
    const float4* rp4 = (const float4*)(road + (size_t)((n * NBR + b) * NP) * 3);
    if (tid < 192) ((float4*)rpt)[tid] = rp4[tid];
    const float4* tj4 = (const float4*)(traj + (size_t)n * TT * 3);
    if (tid >= 160) ((float4*)tbuf)[tid - 160] = tj4[tid - 160];
    // mask dtype: lengths>=2 => element (0,0,1) true. int32 LE => byte[1]==0.
    if (maskraw[1] == 0) {
        rm[tid] = (unsigned char)(((const int*)maskraw)[(size_t)(n * NBR + b) * NP + tid] != 0);
    } else {
        rm[tid] = (unsigned char)(maskraw[(size_t)(n * NBR + b) * NP + tid] != 0);
    }
    __syncthreads();                                            // B1

    // ---- fwd segment lengths (masked), traj segment lengths
    float slv = 0.0f;
    bool  smv = false;
    if (tid < NS) {
        smv = (rm[tid] != 0) && (rm[tid + 1] != 0);
        float dx = rpt[3 * tid + 3] - rpt[3 * tid + 0];
        float dy = rpt[3 * tid + 4] - rpt[3 * tid + 1];
        float dz = rpt[3 * tid + 5] - rpt[3 * tid + 2];
        slv = smv ? sqrtf(dx * dx + dy * dy + dz * dz) : 0.0f;
    }
    sl[tid] = slv;

    float tlv = 0.0f;
    if (tid < TT - 1) {
        float dx = tbuf[3 * tid + 3] - tbuf[3 * tid + 0];
        float dy = tbuf[3 * tid + 4] - tbuf[3 * tid + 1];
        float dz = tbuf[3 * tid + 5] - tbuf[3 * tid + 2];
        tlv = sqrtf(dx * dx + dy * dy + dz * dz);
    }

    // ---- joint warp-shuffle inclusive scans
    float vA = slv, vB = tlv;
    #pragma unroll
    for (int off = 1; off < 32; off <<= 1) {
        float tA = __shfl_up_sync(FULLMASK, vA, off);
        float tB = __shfl_up_sync(FULLMASK, vB, off);
        if (lane >= off) { vA += tA; vB += tB; }
    }
    if (lane == 31) { wsA[w] = vA; wsB[w] = vB; }
    __syncthreads();                                            // B2
    {
        float offA = 0.0f, offB = 0.0f;
        #pragma unroll
        for (int k = 0; k < 7; ++k) {
            if (k < w) { offA += wsA[k]; offB += wsB[k]; }
        }
        cum[tid] = vA + offA;
        if (tid < TT) tcs_s[tid] = vB + offB;
    }

    // ---- p0 projection d2 per fwd segment; CTA argmin via redux+ballot+smem atomic
    const float p0x = tbuf[0], p0y = tbuf[1], p0z = tbuf[2];
    float d2 = BIGF;
    if (tid < NS && smv) {
        float ax = rpt[3 * tid + 0], ay = rpt[3 * tid + 1], az = rpt[3 * tid + 2];
        float svx = rpt[3 * tid + 3] - ax, svy = rpt[3 * tid + 4] - ay, svz = rpt[3 * tid + 5] - az;
        float svdot = fmaxf(svx * svx + svy * svy + svz * svz, 1e-12f);
        float t0 = ((p0x - ax) * svx + (p0y - ay) * svy + (p0z - az) * svz) / svdot;
        t0 = fminf(fmaxf(t0, 0.0f), 1.0f);
        float qx = ax + t0 * svx, qy = ay + t0 * svy, qz = az + t0 * svz;
        float ex = p0x - qx, ey = p0y - qy, ez = p0z - qz;
        d2 = ex * ex + ey * ey + ez * ez;
    }
    {
        unsigned bits = __float_as_uint(d2);            // d2>=0 => order-preserving
        unsigned wmin = __reduce_min_sync(FULLMASK, bits);
        unsigned ball = __ballot_sync(FULLMASK, bits == wmin);
        if (lane == 0) {
            int idx = (w << 5) + (__ffs(ball) - 1);
            atomicMin(&s_key, ((unsigned long long)wmin << 32) | (unsigned)idx);
        }
        unsigned vb = __ballot_sync(FULLMASK, smv);
        if (lane == 0 && vb) {
            atomicMin(&s_mn, (w << 5) + (__ffs(vb) - 1));
            atomicMax(&s_mx, (w << 5) + (32 - __clz(vb)));
        }
    }
    __syncthreads();                                            // B3

    const int  seg0 = (int)(unsigned)(s_key & 0xFFFFFFFFull);
    const int  fmx  = s_mx;
    const int  fmn  = s_mn;
    const bool has  = (fmx > 0);
    const int  mvjF = has ? (fmx - 1) : 0;
    const int  mvjB = has ? (NS - 1 - fmn) : 0;

    const float total = cum[NP - 1];
    float entryF;
    {
        int k = seg0;
        float ax = rpt[3 * k + 0], ay = rpt[3 * k + 1], az = rpt[3 * k + 2];
        float svx = rpt[3 * k + 3] - ax, svy = rpt[3 * k + 4] - ay, svz = rpt[3 * k + 5] - az;
        float svdot = fmaxf(svx * svx + svy * svy + svz * svz, 1e-12f);
        float t0 = ((p0x - ax) * svx + (p0y - ay) * svy + (p0z - az) * svz) / svdot;
        t0 = fminf(fmaxf(t0, 0.0f), 1.0f);
        float c0 = (k == 0) ? 0.0f : cum[k - 1];
        entryF = c0 + t0 * sl[k];
    }

    // ---- walks: warps 0-3 fwd (b2=b), warps 4-7 bwd (b2=b+16)
    const bool  isB = (tid >= TT);
    const int   t   = tid & (TT - 1);
    const float entry = isB ? (total - entryF) : entryF;
    const int   mvj   = isB ? mvjB : mvjF;

    float tcv = (t == 0) ? 0.0f : tcs_s[t - 1];
    float tgt = fmaxf(fminf(entry + tcv, total), 0.0f);

    //  fwd: largest k with cum_s(k) <= tgt
    //  bwd: largest k with cum_s(k) <  u (u = total - tgt); j = u>0 ? 254-k : 255
    const float T = isB ? (total - tgt) : tgt;
    int k = 0;
    #pragma unroll
    for (int step = 128; step > 0; step >>= 1) {
        int nj = k + step;                   // nj <= 255
        float v = cum[nj - 1];
        bool ok = isB ? (v < T) : (v <= T);  // isB warp-uniform
        if (ok) k = nj;
    }
    int j = isB ? ((T > 0.0f) ? (NS - 1 - k) : NS) : k;
    j = min(j, mvj);

    float cj  = (j == 0) ? 0.0f : (isB ? (total - cum[NS - 1 - j]) : cum[j - 1]);
    float slj = isB ? sl[NS - 1 - j] : sl[j];
    float tl  = fminf(fmaxf((tgt - cj) / fmaxf(slj, 1e-9f), 0.0f), 1.0f);
    float prx, pry, prz;
    if (isB) {
        int r = NP - 1 - j;                  // a_bw[j]=P[255-j], next=P[254-j]
        float ax = rpt[3 * r + 0], ay = rpt[3 * r + 1], az = rpt[3 * r + 2];
        prx = ax + tl * (rpt[3 * r - 3] - ax);
        pry = ay + tl * (rpt[3 * r - 2] - ay);
        prz = az + tl * (rpt[3 * r - 1] - az);
    } else {
        float ax = rpt[3 * j + 0], ay = rpt[3 * j + 1], az = rpt[3 * j + 2];
        prx = ax + tl * (rpt[3 * j + 3] - ax);
        pry = ay + tl * (rpt[3 * j + 4] - ay);
        prz = az + tl * (rpt[3 * j + 5] - az);
    }
    // stage proj in smem (AoS, fwd half then bwd half)
    stage[3 * tid + 0] = prx;
    stage[3 * tid + 1] = pry;
    stage[3 * tid + 2] = prz;

    float dx = tbuf[3 * t + 0] - prx, dy = tbuf[3 * t + 1] - pry, dz = tbuf[3 * t + 2] - prz;
    float dist = sqrtf(dx * dx + dy * dy + dz * dz);

    // deterministic dist sums (warp shfl + fixed-order combine)
    #pragma unroll
    for (int off = 16; off > 0; off >>= 1)
        dist += __shfl_xor_sync(FULLMASK, dist, off);
    if (lane == 0) wsum[w] = dist;
    __syncthreads();                                            // B4 (stage+wsum ready)

    // coalesced g_proj write: 96 float4 per branch
    {
        if (tid < 96) {
            float4* gp4 = (float4*)(g_proj + (size_t)(n * NB2 + b) * TT * 3);
            gp4[tid] = ((const float4*)stage)[tid];
        } else if (tid < 192) {
            float4* gp4 = (float4*)(g_proj + (size_t)(n * NB2 + b + NBR) * TT * 3);
            gp4[tid - 96] = ((const float4*)stage)[tid];
        }
    }
    __syncthreads();                                            // B5 (STGs issued by all)

    if (tid == 0) {
        float cf = wsum[0] + wsum[1] + wsum[2] + wsum[3];
        float cb = wsum[4] + wsum[5] + wsum[6] + wsum[7];
        g_cost[n * NB2 + b]       = has ? cf : BIGF;
        g_cost[n * NB2 + b + NBR] = has ? cb : BIGF;
        __threadfence();                       // release g_proj + g_cost
        int old = atomicAdd(&g_cnt[n], 1);
        sh_pick = (old == NBR - 1);
    }
    __syncthreads();                                            // B6

    if (!sh_pick) return;

    // ---- picker CTA for sample n: 32-way argmin + coalesced gather
    __threadfence();                           // acquire
    if (w == 0) {
        float cv = __ldcg(&g_cost[n * NB2 + lane]);
        float pbd = cv; int pbi = lane;
        #pragma unroll
        for (int off = 16; off > 0; off >>= 1) {
            float od = __shfl_xor_sync(FULLMASK, pbd, off);
            int   oi = __shfl_xor_sync(FULLMASK, pbi, off);
            if (od < pbd || (od == pbd && oi < pbi)) { pbd = od; pbi = oi; }
        }
        if (lane == 0) { sh_b = pbi; sh_hasb = (pbd < BIGF); }
    }
    __syncthreads();                                            // B7

    if (tid < 96) {
        float4* out4 = (float4*)(out + (size_t)n * TT * 3);
        if (sh_hasb) {
            const float* gp = g_proj + (size_t)(n * NB2 + sh_b) * TT * 3;
            float4 v;
            v.x = __ldcg(&gp[4 * tid + 0]);
            v.y = __ldcg(&gp[4 * tid + 1]);
            v.z = __ldcg(&gp[4 * tid + 2]);
            v.w = __ldcg(&gp[4 * tid + 3]);
            out4[tid] = v;
        } else {
            out4[tid] = ((const float4*)tbuf)[tid];
        }
    }
    if (tid == 0) g_cnt[n] = 0;                // reset for next graph replay
}

extern "C" void kernel_launch(void* const* d_in, const int* in_sizes, int n_in,
                              void* d_out, int out_size)
{
    const float*         traj = (const float*)d_in[0];
    const float*         road = (const float*)d_in[1];
    const unsigned char* mask = (const unsigned char*)d_in[2];
    float* out = (float*)d_out;

    dim3 grid(NBR, NN);
    fused_arc_kernel<<<grid, 256>>>(traj, road, mask, out);
}